// round 13
// baseline (speedup 1.0000x reference)
#include <cuda_runtime.h>
#include <cuda_bf16.h>
#include <cuda_fp16.h>
#include <cstdint>
#include <math.h>

// ---------------------------------------------------------------------------
// StaticSelfAttention: B=1, S=2048, DIM=5120, H=40, D=128, fp32.
// Round 12: FA v5 — Br=128 (halved K/V traffic), log2-domain softmax with
//           ex2.approx.f16x2, row-sums via ones-mma. GEMMs unchanged.
// ---------------------------------------------------------------------------

#define S_LEN 2048
#define DIM   5120
#define NHEAD 40
#define HDIM  128
#define QKVW  (3*DIM)          // 15360
#define EPS   1e-6f
// ATT_SCALE * log2(e): folded into q at normrope; QK scores land in log2 domain
#define QSCALE 0.127517445f

// -------------------- scratch (__device__ globals; no allocs) --------------
__device__ __half g_hsH[(size_t)S_LEN * DIM];              // hs fp16
__device__ __half g_qk [(size_t)S_LEN * 2 * DIM];          // q,k fp16 [S][2*DIM]
__device__ __half g_attF[(size_t)S_LEN * DIM];             // FA out fp16
__device__ __half g_wqkvT[(size_t)QKVW * DIM];             // [N][K] fp16
__device__ __half g_woutT[(size_t)DIM  * DIM];             // [N][K] fp16
__device__ __half g_qF[(size_t)S_LEN * NHEAD * HDIM];      // [s][h][d] fp16 (pre-scaled)
__device__ __half g_kF[(size_t)S_LEN * NHEAD * HDIM];      // [s][h][d] fp16
__device__ __half g_vH[(size_t)S_LEN * DIM];               // [s][h*128+d] fp16

// -------------------- PTX helpers (baseline ISA only) ----------------------
__device__ __forceinline__ uint32_t smem_u32(const void* p) {
    uint32_t a;
    asm("{ .reg .u64 t; cvta.to.shared.u64 t, %1; cvt.u32.u64 %0, t; }"
        : "=r"(a) : "l"(p));
    return a;
}
__device__ __forceinline__ void cp16(uint32_t dst, const void* src) {
    asm volatile("cp.async.cg.shared.global [%0], [%1], 16;\n"
                 :: "r"(dst), "l"(src));
}
#define CP_COMMIT() asm volatile("cp.async.commit_group;\n" ::: "memory")
#define CP_WAIT2()  asm volatile("cp.async.wait_group 2;\n" ::: "memory")
#define CP_WAIT1()  asm volatile("cp.async.wait_group 1;\n" ::: "memory")
#define CP_WAIT0()  asm volatile("cp.async.wait_group 0;\n" ::: "memory")

__device__ __forceinline__ void ldm_x4(uint32_t* r, uint32_t a) {
    asm volatile("ldmatrix.sync.aligned.m8n8.x4.shared.b16 {%0,%1,%2,%3}, [%4];\n"
                 : "=r"(r[0]), "=r"(r[1]), "=r"(r[2]), "=r"(r[3]) : "r"(a));
}
__device__ __forceinline__ void ldm_x4t(uint32_t* r, uint32_t a) {
    asm volatile("ldmatrix.sync.aligned.m8n8.x4.trans.shared.b16 {%0,%1,%2,%3}, [%4];\n"
                 : "=r"(r[0]), "=r"(r[1]), "=r"(r[2]), "=r"(r[3]) : "r"(a));
}
__device__ __forceinline__ void mma_f16(float* d, const uint32_t* a,
                                        const uint32_t* b) {
    asm volatile(
        "mma.sync.aligned.m16n8k16.row.col.f32.f16.f16.f32 "
        "{%0,%1,%2,%3}, {%4,%5,%6,%7}, {%8,%9}, {%0,%1,%2,%3};\n"
        : "+f"(d[0]), "+f"(d[1]), "+f"(d[2]), "+f"(d[3])
        : "r"(a[0]), "r"(a[1]), "r"(a[2]), "r"(a[3]), "r"(b[0]), "r"(b[1]));
}
// pack (x -> lo, y -> hi) to fp16x2 and take 2^each
__device__ __forceinline__ uint32_t exp2_h2(float x, float y) {
    uint32_t p, r;
    asm("cvt.rn.f16x2.f32 %0, %1, %2;" : "=r"(p) : "f"(y), "f"(x));
    asm("ex2.approx.f16x2 %0, %1;" : "=r"(r) : "r"(p));
    return r;
}
__device__ __forceinline__ float exp2_f(float x) {
    float r;
    asm("ex2.approx.ftz.f32 %0, %1;" : "=f"(r) : "f"(x));
    return r;
}

// ===========================================================================
// Pre-pass 1: fp32 -> fp16 elementwise
// ===========================================================================
__global__ __launch_bounds__(256) void convert_h(
    const float* __restrict__ X, __half* __restrict__ Y, int n2)
{
    for (int i = blockIdx.x * 256 + threadIdx.x; i < n2;
         i += gridDim.x * 256) {
        float2 v = ((const float2*)X)[i];
        ((__half2*)Y)[i] = __floats2half2_rn(v.x, v.y);
    }
}

// ===========================================================================
// Pre-pass 2: W[K=DIM][N] fp32 -> T[N][K=DIM] fp16
// ===========================================================================
__global__ void transpose_h(const float* __restrict__ W,
                            __half* __restrict__ T, int N)
{
    __shared__ float t[32][33];
    const int n0 = blockIdx.x * 32, k0 = blockIdx.y * 32;
    const int x = threadIdx.x, y = threadIdx.y;   // 32 x 8
    #pragma unroll
    for (int i = 0; i < 32; i += 8)
        t[y + i][x] = W[(size_t)(k0 + y + i) * N + n0 + x];
    __syncthreads();
    #pragma unroll
    for (int i = 0; i < 32; i += 8)
        T[(size_t)(n0 + y + i) * DIM + k0 + x] = __float2half_rn(t[x][y + i]);
}

// ===========================================================================
// fp16 GEMM (unchanged from round 11; tensor=82%).
// ===========================================================================
#define G_BK      32
#define G_STAGES  4
#define G_STAGE_B 16384
#define G_SMEM    (G_STAGES * G_STAGE_B)

__device__ __forceinline__ uint32_t sw_off(int r, int c) {
    return (uint32_t)(((r << 2) | (c ^ ((r >> 1) & 3))) << 4);
}

__global__ __launch_bounds__(128, 2) void gemm_h(
    const __half* __restrict__ A, const __half* __restrict__ Bm,
    const float* __restrict__ bias, float* __restrict__ C,
    __half* __restrict__ qkout, __half* __restrict__ vout, int N, int K)
{
    extern __shared__ char smraw[];
    const uint32_t sbase = smem_u32(smraw);

    const int tid = threadIdx.x, lane = tid & 31, wid = tid >> 5;
    const int row0 = blockIdx.x * 128;
    const int col0 = blockIdx.y * 128;
    const int mw = (wid >> 1) * 64;
    const int nw = (wid & 1) * 64;
    const int sub = lane >> 3, l7 = lane & 7;

    float acc[4][8][4];
    #pragma unroll
    for (int i = 0; i < 4; i++)
        #pragma unroll
        for (int j = 0; j < 8; j++)
            #pragma unroll
            for (int q = 0; q < 4; q++) acc[i][j][q] = 0.f;

    const int NIT = K / G_BK;

    auto load_stage = [&](int st, int k0) {
        const uint32_t sA = sbase + st * G_STAGE_B;
        const uint32_t sB = sA + 8192;
        #pragma unroll
        for (int i = 0; i < 4; i++) {
            int f = tid + i * 128;
            int r = f >> 2, c = f & 3;
            uint32_t so = sw_off(r, c);
            cp16(sA + so, A  + (size_t)(row0 + r) * K + k0 + c * 8);
            cp16(sB + so, Bm + (size_t)(col0 + r) * K + k0 + c * 8);
        }
    };

    #pragma unroll
    for (int s = 0; s < G_STAGES - 1; s++) { load_stage(s, s * G_BK); CP_COMMIT(); }

    #pragma unroll 1
    for (int it = 0; it < NIT; it++) {
        CP_WAIT2();
        __syncthreads();
        const uint32_t uA = sbase + (it & 3) * G_STAGE_B;
        const uint32_t uB = uA + 8192;

        #pragma unroll
        for (int kk = 0; kk < 2; kk++) {
            const int c0 = kk * 2;
            uint32_t a[4][4], b[4][4];
            #pragma unroll
            for (int i = 0; i < 4; i++) {
                int r = mw + i * 16 + ((sub & 1) << 3) + l7;
                int c = c0 + (sub >> 1);
                ldm_x4(a[i], uA + sw_off(r, c));
            }
            #pragma unroll
            for (int p = 0; p < 4; p++) {
                int r = nw + p * 16 + ((sub >> 1) << 3) + l7;
                int c = c0 + (sub & 1);
                ldm_x4(b[p], uB + sw_off(r, c));
            }
            #pragma unroll
            for (int i = 0; i < 4; i++)
                #pragma unroll
                for (int j = 0; j < 8; j++)
                    mma_f16(acc[i][j], a[i], &b[j >> 1][(j & 1) * 2]);
        }

        const int nld = it + G_STAGES - 1;
        if (nld < NIT) load_stage(nld & 3, nld * G_BK);
        CP_COMMIT();
    }

    const int g = lane >> 2, tq = lane & 3;
    #pragma unroll
    for (int i = 0; i < 4; i++) {
        int r = row0 + mw + i * 16 + g;
        #pragma unroll
        for (int j = 0; j < 8; j++) {
            int c = col0 + nw + j * 8 + tq * 2;
            float bx = bias[c], by = bias[c + 1];
            float x0 = acc[i][j][0] + bx, y0 = acc[i][j][1] + by;
            float x1 = acc[i][j][2] + bx, y1 = acc[i][j][3] + by;
            if (qkout != nullptr) {
                if (col0 < 2 * DIM) {
                    *(__half2*)(qkout + (size_t)r * (2 * DIM) + c)
                        = __floats2half2_rn(x0, y0);
                    *(__half2*)(qkout + (size_t)(r + 8) * (2 * DIM) + c)
                        = __floats2half2_rn(x1, y1);
                } else {
                    int vc = c - 2 * DIM;
                    *(__half2*)(vout + (size_t)r * DIM + vc)
                        = __floats2half2_rn(x0, y0);
                    *(__half2*)(vout + (size_t)(r + 8) * DIM + vc)
                        = __floats2half2_rn(x1, y1);
                }
            } else {
                float2 o0; o0.x = x0; o0.y = y0;
                float2 o1; o1.x = x1; o1.y = y1;
                *(float2*)(C + (size_t)r * N + c)       = o0;
                *(float2*)(C + (size_t)(r + 8) * N + c) = o1;
            }
        }
    }
}

// ===========================================================================
// Fused RMSNorm + RoPE -> fp16 per-head q/k; q pre-scaled by ATT_SCALE*log2e.
// ===========================================================================
__global__ __launch_bounds__(256) void normrope_kernel(
    const __half* __restrict__ qk,
    const float* __restrict__ w_qn, const float* __restrict__ w_kn,
    const float* __restrict__ cosf, const float* __restrict__ sinf,
    __half* __restrict__ qF, __half* __restrict__ kF)
{
    const int s   = blockIdx.x;
    const int sel = blockIdx.y;
    const int tid = threadIdx.x;

    const __half* row = qk + (size_t)s * (2 * DIM) + sel * DIM;
    const float* w = sel ? w_kn : w_qn;
    __half* dst = sel ? kF : qF;
    const float oscale = sel ? 1.f : QSCALE;

    const int lane = tid & 31, wid = tid >> 5;
    __shared__ float red[8];
    __shared__ float s_rstd;

    float ss = 0.f;
    const __half2* row2 = (const __half2*)row;
    for (int i = tid; i < DIM / 2; i += 256) {
        float2 v = __half22float2(row2[i]);
        ss += v.x * v.x + v.y * v.y;
    }
    #pragma unroll
    for (int o = 16; o; o >>= 1) ss += __shfl_xor_sync(0xffffffffu, ss, o);
    if (lane == 0) red[wid] = ss;
    __syncthreads();
    if (tid == 0) {
        float t = 0.f;
        #pragma unroll
        for (int i = 0; i < 8; i++) t += red[i];
        s_rstd = rsqrtf(t / (float)DIM + EPS);
    }
    __syncthreads();
    const float rstd = s_rstd;

    const float* crow = cosf + (size_t)s * HDIM;
    const float* srow = sinf + (size_t)s * HDIM;
    for (int p = tid; p < DIM / 2; p += 256) {
        int head = p >> 6;
        int t    = p & 63;
        int e0 = head * HDIM + 2 * t;
        float2 x = __half22float2(row2[p]);
        float xe = x.x * rstd * w[e0];
        float xo = x.y * rstd * w[e0 + 1];
        float c  = crow[2 * t];
        float sn = srow[2 * t + 1];
        float oe = (xe * c - xo * sn) * oscale;
        float oo = (xe * sn + xo * c) * oscale;

        __half* out = dst + ((size_t)s * NHEAD + head) * HDIM + 2 * t;
        *(__half2*)out = __floats2half2_rn(oe, oo);
    }
}

// ===========================================================================
// Flash attention v5: Br=128 (8 warps, 256 thr, 1 CTA/SM), Bc=64.
//   Scores arrive in log2 domain (q pre-scaled). P via ex2.approx.f16x2.
//   Row sums l via ones-mma (exact fp32 sum of applied fp16 P).
// ===========================================================================
#define FD_NT   (S_LEN / 64)       // 32
#define ROWB    272                // 17 x 16B chunks (16 data + 1 pad)
#define FD_K(st) ((st) * 17408)
#define FD_V(st) (34816 + (st) * 17408)
#define FD_SMEM 69632

__global__ __launch_bounds__(256, 1) void fa_mma(
    const __half* __restrict__ qF, const __half* __restrict__ kF,
    const __half* __restrict__ vH, __half* __restrict__ att)
{
    extern __shared__ char smraw[];
    const uint32_t sb = smem_u32(smraw);
    const int tid = threadIdx.x, lane = tid & 31, w = tid >> 5;
    const int sub = lane >> 3, l7 = lane & 7;
    const int q0 = blockIdx.x * 128, h = blockIdx.y;
    const int mw = w * 16;

    // ---- stage Q tile (128 rows) through K0+K1 buffers, ldmatrix to regs --
    #pragma unroll
    for (int i = 0; i < 8; i++) {
        int f = tid + i * 256, r = f >> 4, c = f & 15;   // 2048 chunks
        cp16(sb + r * ROWB + c * 16,
             qF + ((size_t)(q0 + r) * NHEAD + h) * HDIM + c * 8);
    }
    CP_COMMIT();
    CP_WAIT0();
    __syncthreads();

    uint32_t qf[8][4];
    {
        const uint32_t qb = sb + (mw + ((sub & 1) << 3) + l7) * ROWB;
        #pragma unroll
        for (int ks = 0; ks < 8; ks++)
            ldm_x4(qf[ks], qb + (2 * ks + (sub >> 1)) * 16);
    }
    __syncthreads();

    auto load_kv = [&](int st, int kt) {
        const int kb = kt * 64;
        #pragma unroll
        for (int i = 0; i < 4; i++) {
            int f = tid + i * 256, r = f >> 4, c = f & 15;  // 1024 chunks
            cp16(sb + FD_K(st) + r * ROWB + c * 16,
                 kF + ((size_t)(kb + r) * NHEAD + h) * HDIM + c * 8);
        }
        #pragma unroll
        for (int i = 0; i < 4; i++) {
            int f = tid + i * 256, r = f >> 4, c = f & 15;
            cp16(sb + FD_V(st) + r * ROWB + c * 16,
                 vH + (size_t)(kb + r) * DIM + h * HDIM + c * 8);
        }
    };
    load_kv(0, 0); CP_COMMIT();
    load_kv(1, 1); CP_COMMIT();

    const uint32_t ones2 = 0x3C003C00u;           // fp16 (1.0, 1.0)
    const uint32_t onesf[2] = { ones2, ones2 };

    float m0 = -1e30f, m1 = -1e30f, l0 = 0.f, l1 = 0.f;
    float oacc[16][4];
    #pragma unroll
    for (int i = 0; i < 16; i++)
        #pragma unroll
        for (int j = 0; j < 4; j++) oacc[i][j] = 0.f;

    #pragma unroll 1
    for (int kt = 0; kt < FD_NT; kt++) {
        CP_WAIT1();
        __syncthreads();
        const uint32_t Ks = sb + FD_K(kt & 1);
        const uint32_t Vs = sb + FD_V(kt & 1);
        const uint32_t kbase = Ks + ((((sub >> 1) << 3)) + l7) * ROWB;

        // ---- S = Q K^T (fp16, scores already in log2 domain) ----
        float s[8][4];
        #pragma unroll
        for (int j = 0; j < 8; j++)
            #pragma unroll
            for (int q = 0; q < 4; q++) s[j][q] = 0.f;

        #pragma unroll
        for (int ks = 0; ks < 8; ks++) {
            const uint32_t ca = (2 * ks + (sub & 1)) * 16;
            #pragma unroll
            for (int p = 0; p < 4; p++) {
                uint32_t bf[4];
                ldm_x4(bf, kbase + p * 16 * ROWB + ca);
                mma_f16(s[2 * p],     qf[ks], bf);
                mma_f16(s[2 * p + 1], qf[ks], bf + 2);
            }
        }

        // ---- softmax in log2 domain ----
        float rmx0 = -1e30f, rmx1 = -1e30f;
        #pragma unroll
        for (int j = 0; j < 8; j++) {
            rmx0 = fmaxf(rmx0, fmaxf(s[j][0], s[j][1]));
            rmx1 = fmaxf(rmx1, fmaxf(s[j][2], s[j][3]));
        }
        rmx0 = fmaxf(rmx0, __shfl_xor_sync(0xffffffffu, rmx0, 1));
        rmx0 = fmaxf(rmx0, __shfl_xor_sync(0xffffffffu, rmx0, 2));
        rmx1 = fmaxf(rmx1, __shfl_xor_sync(0xffffffffu, rmx1, 1));
        rmx1 = fmaxf(rmx1, __shfl_xor_sync(0xffffffffu, rmx1, 2));

        float nm0 = fmaxf(m0, rmx0), nm1 = fmaxf(m1, rmx1);
        float a0 = exp2_f(m0 - nm0), a1 = exp2_f(m1 - nm1);
        m0 = nm0; m1 = nm1;

        // P = 2^(s - m) as fp16 pairs, directly in PV A-fragment layout
        uint32_t pa[8], pb[8];
        #pragma unroll
        for (int j = 0; j < 8; j++) {
            pa[j] = exp2_h2(s[j][0] - nm0, s[j][1] - nm0);
            pb[j] = exp2_h2(s[j][2] - nm1, s[j][3] - nm1);
        }

        #pragma unroll
        for (int nb = 0; nb < 16; nb++) {
            oacc[nb][0] *= a0; oacc[nb][1] *= a0;
            oacc[nb][2] *= a1; oacc[nb][3] *= a1;
        }

        // ---- O += P @ V ; l via ones-mma (exact sums of applied P) ----
        float lacc[4] = {0.f, 0.f, 0.f, 0.f};
        #pragma unroll
        for (int kb = 0; kb < 4; kb++) {
            uint32_t a[4];
            a[0] = pa[2 * kb];     a[1] = pb[2 * kb];
            a[2] = pa[2 * kb + 1]; a[3] = pb[2 * kb + 1];
            mma_f16(lacc, a, onesf);
            const uint32_t vb = Vs + (kb * 16 + ((sub & 1) << 3) + l7) * ROWB
                              + (((sub >> 1) << 3)) * 2;
            #pragma unroll
            for (int nb = 0; nb < 16; nb += 2) {
                uint32_t bf[4];
                ldm_x4t(bf, vb + nb * 16);
                mma_f16(oacc[nb],     a, bf);
                mma_f16(oacc[nb + 1], a, bf + 2);
            }
        }
        l0 = l0 * a0 + lacc[0];
        l1 = l1 * a1 + lacc[2];

        __syncthreads();
        if (kt + 2 < FD_NT) load_kv(kt & 1, kt + 2);
        CP_COMMIT();
    }

    // ---- epilogue: O/l -> att fp16 ----
    const int g = lane >> 2, tq = lane & 3;
    const float inv0 = 1.f / l0, inv1 = 1.f / l1;
    __half* r0p = att + (size_t)(q0 + mw + g) * DIM + h * HDIM;
    __half* r1p = att + (size_t)(q0 + mw + g + 8) * DIM + h * HDIM;
    #pragma unroll
    for (int nb = 0; nb < 16; nb++) {
        int c = nb * 8 + tq * 2;
        *(__half2*)(r0p + c) =
            __floats2half2_rn(oacc[nb][0] * inv0, oacc[nb][1] * inv0);
        *(__half2*)(r1p + c) =
            __floats2half2_rn(oacc[nb][2] * inv1, oacc[nb][3] * inv1);
    }
}

// ===========================================================================
// kernel_launch
// ===========================================================================
extern "C" void kernel_launch(void* const* d_in, const int* in_sizes, int n_in,
                              void* d_out, int out_size)
{
    const float* hs     = (const float*)d_in[0];
    const float* cosf_  = (const float*)d_in[1];
    const float* sinf_  = (const float*)d_in[2];
    const float* w_qkv  = (const float*)d_in[3];
    const float* b_qkv  = (const float*)d_in[4];
    const float* w_qn   = (const float*)d_in[5];
    const float* w_kn   = (const float*)d_in[6];
    const float* w_out  = (const float*)d_in[7];
    const float* b_out  = (const float*)d_in[8];
    float* out = (float*)d_out;

    __half *hsH, *qk, *attF, *wqkvT, *woutT, *qF, *kF, *vH;
    cudaGetSymbolAddress((void**)&hsH,   g_hsH);
    cudaGetSymbolAddress((void**)&qk,    g_qk);
    cudaGetSymbolAddress((void**)&attF,  g_attF);
    cudaGetSymbolAddress((void**)&wqkvT, g_wqkvT);
    cudaGetSymbolAddress((void**)&woutT, g_woutT);
    cudaGetSymbolAddress((void**)&qF,    g_qF);
    cudaGetSymbolAddress((void**)&kF,    g_kF);
    cudaGetSymbolAddress((void**)&vH,    g_vH);

    cudaFuncSetAttribute(gemm_h,
                         cudaFuncAttributeMaxDynamicSharedMemorySize, G_SMEM);
    cudaFuncSetAttribute(fa_mma,
                         cudaFuncAttributeMaxDynamicSharedMemorySize, FD_SMEM);

    // --- pre-passes: weight transposes (fp16) + hs convert ---
    transpose_h<<<dim3(QKVW/32, DIM/32), dim3(32,8)>>>(w_qkv, wqkvT, QKVW);
    transpose_h<<<dim3(DIM/32,  DIM/32), dim3(32,8)>>>(w_out, woutT, DIM);
    convert_h<<<2048, 256>>>(hs, hsH, (S_LEN*DIM)/2);

    // --- qkv = hs @ w_qkv + b  (fp16; q,k -> g_qk, v -> vH) ---
    gemm_h<<<dim3(S_LEN/128, QKVW/128), 128, G_SMEM>>>(
        hsH, wqkvT, b_qkv, nullptr, qk, vH, QKVW, DIM);

    // --- rmsnorm + rope -> fp16 q/k per head (q pre-scaled) ---
    normrope_kernel<<<dim3(S_LEN, 2), 256>>>(qk, w_qn, w_kn, cosf_, sinf_,
                                             qF, kF);

    // --- flash attention v5 -> att fp16 ---
    fa_mma<<<dim3(S_LEN/128, NHEAD), 256, FD_SMEM>>>(qF, kF, vH, attF);

    // --- out = att @ w_out + b  (fp16 in, fp32 out) ---
    gemm_h<<<dim3(S_LEN/128, DIM/128), 128, G_SMEM>>>(
        attF, woutT, b_out, out, nullptr, nullptr, DIM, DIM);
}

// round 14
// speedup vs baseline: 1.0211x; 1.0211x over previous
#include <cuda_runtime.h>
#include <cuda_bf16.h>
#include <cuda_fp16.h>
#include <cstdint>
#include <math.h>

// ---------------------------------------------------------------------------
// StaticSelfAttention: B=1, S=2048, DIM=5120, H=40, D=128, fp32.
// Round 14: round-11 structure restored; FA keeps only the two safe wins:
//           q pre-scaled by ATT_SCALE, row-sums l via ones-mma. f32 expf.
// ---------------------------------------------------------------------------

#define S_LEN 2048
#define DIM   5120
#define NHEAD 40
#define HDIM  128
#define QKVW  (3*DIM)          // 15360
#define EPS   1e-6f
#define ATT_SCALE 0.08838834764831845f   // 128^-0.5 (folded into q)

// -------------------- scratch (__device__ globals; no allocs) --------------
__device__ __half g_hsH[(size_t)S_LEN * DIM];              // hs fp16
__device__ __half g_qk [(size_t)S_LEN * 2 * DIM];          // q,k fp16 [S][2*DIM]
__device__ __half g_attF[(size_t)S_LEN * DIM];             // FA out fp16
__device__ __half g_wqkvT[(size_t)QKVW * DIM];             // [N][K] fp16
__device__ __half g_woutT[(size_t)DIM  * DIM];             // [N][K] fp16
__device__ __half g_qF[(size_t)S_LEN * NHEAD * HDIM];      // [s][h][d] fp16 (pre-scaled)
__device__ __half g_kF[(size_t)S_LEN * NHEAD * HDIM];      // [s][h][d] fp16
__device__ __half g_vH[(size_t)S_LEN * DIM];               // [s][h*128+d] fp16

// -------------------- PTX helpers (baseline ISA only) ----------------------
__device__ __forceinline__ uint32_t smem_u32(const void* p) {
    uint32_t a;
    asm("{ .reg .u64 t; cvta.to.shared.u64 t, %1; cvt.u32.u64 %0, t; }"
        : "=r"(a) : "l"(p));
    return a;
}
__device__ __forceinline__ void cp16(uint32_t dst, const void* src) {
    asm volatile("cp.async.cg.shared.global [%0], [%1], 16;\n"
                 :: "r"(dst), "l"(src));
}
#define CP_COMMIT() asm volatile("cp.async.commit_group;\n" ::: "memory")
#define CP_WAIT2()  asm volatile("cp.async.wait_group 2;\n" ::: "memory")
#define CP_WAIT1()  asm volatile("cp.async.wait_group 1;\n" ::: "memory")
#define CP_WAIT0()  asm volatile("cp.async.wait_group 0;\n" ::: "memory")

__device__ __forceinline__ void ldm_x4(uint32_t* r, uint32_t a) {
    asm volatile("ldmatrix.sync.aligned.m8n8.x4.shared.b16 {%0,%1,%2,%3}, [%4];\n"
                 : "=r"(r[0]), "=r"(r[1]), "=r"(r[2]), "=r"(r[3]) : "r"(a));
}
__device__ __forceinline__ void ldm_x4t(uint32_t* r, uint32_t a) {
    asm volatile("ldmatrix.sync.aligned.m8n8.x4.trans.shared.b16 {%0,%1,%2,%3}, [%4];\n"
                 : "=r"(r[0]), "=r"(r[1]), "=r"(r[2]), "=r"(r[3]) : "r"(a));
}
__device__ __forceinline__ void mma_f16(float* d, const uint32_t* a,
                                        const uint32_t* b) {
    asm volatile(
        "mma.sync.aligned.m16n8k16.row.col.f32.f16.f16.f32 "
        "{%0,%1,%2,%3}, {%4,%5,%6,%7}, {%8,%9}, {%0,%1,%2,%3};\n"
        : "+f"(d[0]), "+f"(d[1]), "+f"(d[2]), "+f"(d[3])
        : "r"(a[0]), "r"(a[1]), "r"(a[2]), "r"(a[3]), "r"(b[0]), "r"(b[1]));
}
__device__ __forceinline__ uint32_t f22h2(float x, float y) {
    __half2 t = __floats2half2_rn(x, y);
    return *reinterpret_cast<uint32_t*>(&t);
}

// ===========================================================================
// Pre-pass 1: fp32 -> fp16 elementwise
// ===========================================================================
__global__ __launch_bounds__(256) void convert_h(
    const float* __restrict__ X, __half* __restrict__ Y, int n2)
{
    for (int i = blockIdx.x * 256 + threadIdx.x; i < n2;
         i += gridDim.x * 256) {
        float2 v = ((const float2*)X)[i];
        ((__half2*)Y)[i] = __floats2half2_rn(v.x, v.y);
    }
}

// ===========================================================================
// Pre-pass 2: W[K=DIM][N] fp32 -> T[N][K=DIM] fp16
// ===========================================================================
__global__ void transpose_h(const float* __restrict__ W,
                            __half* __restrict__ T, int N)
{
    __shared__ float t[32][33];
    const int n0 = blockIdx.x * 32, k0 = blockIdx.y * 32;
    const int x = threadIdx.x, y = threadIdx.y;   // 32 x 8
    #pragma unroll
    for (int i = 0; i < 32; i += 8)
        t[y + i][x] = W[(size_t)(k0 + y + i) * N + n0 + x];
    __syncthreads();
    #pragma unroll
    for (int i = 0; i < 32; i += 8)
        T[(size_t)(n0 + y + i) * DIM + k0 + x] = __float2half_rn(t[x][y + i]);
}

// ===========================================================================
// fp16 GEMM (unchanged; tensor=82%).
// ===========================================================================
#define G_BK      32
#define G_STAGES  4
#define G_STAGE_B 16384
#define G_SMEM    (G_STAGES * G_STAGE_B)

__device__ __forceinline__ uint32_t sw_off(int r, int c) {
    return (uint32_t)(((r << 2) | (c ^ ((r >> 1) & 3))) << 4);
}

__global__ __launch_bounds__(128, 2) void gemm_h(
    const __half* __restrict__ A, const __half* __restrict__ Bm,
    const float* __restrict__ bias, float* __restrict__ C,
    __half* __restrict__ qkout, __half* __restrict__ vout, int N, int K)
{
    extern __shared__ char smraw[];
    const uint32_t sbase = smem_u32(smraw);

    const int tid = threadIdx.x, lane = tid & 31, wid = tid >> 5;
    const int row0 = blockIdx.x * 128;
    const int col0 = blockIdx.y * 128;
    const int mw = (wid >> 1) * 64;
    const int nw = (wid & 1) * 64;
    const int sub = lane >> 3, l7 = lane & 7;

    float acc[4][8][4];
    #pragma unroll
    for (int i = 0; i < 4; i++)
        #pragma unroll
        for (int j = 0; j < 8; j++)
            #pragma unroll
            for (int q = 0; q < 4; q++) acc[i][j][q] = 0.f;

    const int NIT = K / G_BK;

    auto load_stage = [&](int st, int k0) {
        const uint32_t sA = sbase + st * G_STAGE_B;
        const uint32_t sB = sA + 8192;
        #pragma unroll
        for (int i = 0; i < 4; i++) {
            int f = tid + i * 128;
            int r = f >> 2, c = f & 3;
            uint32_t so = sw_off(r, c);
            cp16(sA + so, A  + (size_t)(row0 + r) * K + k0 + c * 8);
            cp16(sB + so, Bm + (size_t)(col0 + r) * K + k0 + c * 8);
        }
    };

    #pragma unroll
    for (int s = 0; s < G_STAGES - 1; s++) { load_stage(s, s * G_BK); CP_COMMIT(); }

    #pragma unroll 1
    for (int it = 0; it < NIT; it++) {
        CP_WAIT2();
        __syncthreads();
        const uint32_t uA = sbase + (it & 3) * G_STAGE_B;
        const uint32_t uB = uA + 8192;

        #pragma unroll
        for (int kk = 0; kk < 2; kk++) {
            const int c0 = kk * 2;
            uint32_t a[4][4], b[4][4];
            #pragma unroll
            for (int i = 0; i < 4; i++) {
                int r = mw + i * 16 + ((sub & 1) << 3) + l7;
                int c = c0 + (sub >> 1);
                ldm_x4(a[i], uA + sw_off(r, c));
            }
            #pragma unroll
            for (int p = 0; p < 4; p++) {
                int r = nw + p * 16 + ((sub >> 1) << 3) + l7;
                int c = c0 + (sub & 1);
                ldm_x4(b[p], uB + sw_off(r, c));
            }
            #pragma unroll
            for (int i = 0; i < 4; i++)
                #pragma unroll
                for (int j = 0; j < 8; j++)
                    mma_f16(acc[i][j], a[i], &b[j >> 1][(j & 1) * 2]);
        }

        const int nld = it + G_STAGES - 1;
        if (nld < NIT) load_stage(nld & 3, nld * G_BK);
        CP_COMMIT();
    }

    const int g = lane >> 2, tq = lane & 3;
    #pragma unroll
    for (int i = 0; i < 4; i++) {
        int r = row0 + mw + i * 16 + g;
        #pragma unroll
        for (int j = 0; j < 8; j++) {
            int c = col0 + nw + j * 8 + tq * 2;
            float bx = bias[c], by = bias[c + 1];
            float x0 = acc[i][j][0] + bx, y0 = acc[i][j][1] + by;
            float x1 = acc[i][j][2] + bx, y1 = acc[i][j][3] + by;
            if (qkout != nullptr) {
                if (col0 < 2 * DIM) {
                    *(__half2*)(qkout + (size_t)r * (2 * DIM) + c)
                        = __floats2half2_rn(x0, y0);
                    *(__half2*)(qkout + (size_t)(r + 8) * (2 * DIM) + c)
                        = __floats2half2_rn(x1, y1);
                } else {
                    int vc = c - 2 * DIM;
                    *(__half2*)(vout + (size_t)r * DIM + vc)
                        = __floats2half2_rn(x0, y0);
                    *(__half2*)(vout + (size_t)(r + 8) * DIM + vc)
                        = __floats2half2_rn(x1, y1);
                }
            } else {
                float2 o0; o0.x = x0; o0.y = y0;
                float2 o1; o1.x = x1; o1.y = y1;
                *(float2*)(C + (size_t)r * N + c)       = o0;
                *(float2*)(C + (size_t)(r + 8) * N + c) = o1;
            }
        }
    }
}

// ===========================================================================
// Fused RMSNorm + RoPE -> fp16 per-head q/k; q pre-scaled by ATT_SCALE.
// ===========================================================================
__global__ __launch_bounds__(256) void normrope_kernel(
    const __half* __restrict__ qk,
    const float* __restrict__ w_qn, const float* __restrict__ w_kn,
    const float* __restrict__ cosf, const float* __restrict__ sinf,
    __half* __restrict__ qF, __half* __restrict__ kF)
{
    const int s   = blockIdx.x;
    const int sel = blockIdx.y;
    const int tid = threadIdx.x;

    const __half* row = qk + (size_t)s * (2 * DIM) + sel * DIM;
    const float* w = sel ? w_kn : w_qn;
    __half* dst = sel ? kF : qF;
    const float oscale = sel ? 1.f : ATT_SCALE;

    const int lane = tid & 31, wid = tid >> 5;
    __shared__ float red[8];
    __shared__ float s_rstd;

    float ss = 0.f;
    const __half2* row2 = (const __half2*)row;
    for (int i = tid; i < DIM / 2; i += 256) {
        float2 v = __half22float2(row2[i]);
        ss += v.x * v.x + v.y * v.y;
    }
    #pragma unroll
    for (int o = 16; o; o >>= 1) ss += __shfl_xor_sync(0xffffffffu, ss, o);
    if (lane == 0) red[wid] = ss;
    __syncthreads();
    if (tid == 0) {
        float t = 0.f;
        #pragma unroll
        for (int i = 0; i < 8; i++) t += red[i];
        s_rstd = rsqrtf(t / (float)DIM + EPS);
    }
    __syncthreads();
    const float rstd = s_rstd;

    const float* crow = cosf + (size_t)s * HDIM;
    const float* srow = sinf + (size_t)s * HDIM;
    for (int p = tid; p < DIM / 2; p += 256) {
        int head = p >> 6;
        int t    = p & 63;
        int e0 = head * HDIM + 2 * t;
        float2 x = __half22float2(row2[p]);
        float xe = x.x * rstd * w[e0];
        float xo = x.y * rstd * w[e0 + 1];
        float c  = crow[2 * t];
        float sn = srow[2 * t + 1];
        float oe = (xe * c - xo * sn) * oscale;
        float oo = (xe * sn + xo * c) * oscale;

        __half* out = dst + ((size_t)s * NHEAD + head) * HDIM + 2 * t;
        *(__half2*)out = __floats2half2_rn(oe, oo);
    }
}

// ===========================================================================
// Flash attention (round-11 structure: Br=64, 128 thr, 2 CTAs/SM).
//   Scores arrive pre-scaled (q folded). f32 __expf softmax.
//   Row sums l via ones-mma (exact fp32 sums of applied fp16 P).
// ===========================================================================
#define FD_NT   (S_LEN / 64)       // 32
#define ROWB    272                // 17 x 16B chunks (16 data + 1 pad)
#define FD_K(st) ((st) * 17408)
#define FD_V(st) (34816 + (st) * 17408)
#define FD_SMEM 69632

__global__ __launch_bounds__(128, 2) void fa_mma(
    const __half* __restrict__ qF, const __half* __restrict__ kF,
    const __half* __restrict__ vH, __half* __restrict__ att)
{
    extern __shared__ char smraw[];
    const uint32_t sb = smem_u32(smraw);
    const int tid = threadIdx.x, lane = tid & 31, w = tid >> 5;
    const int sub = lane >> 3, l7 = lane & 7;
    const int q0 = blockIdx.x * 64, h = blockIdx.y;
    const int mw = w * 16;

    // ---- stage Q tile through K0 buffer, then ldmatrix into registers ----
    #pragma unroll
    for (int i = 0; i < 8; i++) {
        int f = tid + i * 128, r = f >> 4, c = f & 15;
        cp16(sb + FD_K(0) + r * ROWB + c * 16,
             qF + ((size_t)(q0 + r) * NHEAD + h) * HDIM + c * 8);
    }
    CP_COMMIT();
    CP_WAIT0();
    __syncthreads();

    uint32_t qf[8][4];
    {
        const uint32_t qb = sb + FD_K(0)
                          + (mw + ((sub & 1) << 3) + l7) * ROWB;
        #pragma unroll
        for (int ks = 0; ks < 8; ks++)
            ldm_x4(qf[ks], qb + (2 * ks + (sub >> 1)) * 16);
    }
    __syncthreads();

    auto load_kv = [&](int st, int kt) {
        const int kb = kt * 64;
        #pragma unroll
        for (int i = 0; i < 8; i++) {
            int f = tid + i * 128, r = f >> 4, c = f & 15;
            cp16(sb + FD_K(st) + r * ROWB + c * 16,
                 kF + ((size_t)(kb + r) * NHEAD + h) * HDIM + c * 8);
        }
        #pragma unroll
        for (int i = 0; i < 8; i++) {
            int f = tid + i * 128, r = f >> 4, c = f & 15;
            cp16(sb + FD_V(st) + r * ROWB + c * 16,
                 vH + (size_t)(kb + r) * DIM + h * HDIM + c * 8);
        }
    };
    load_kv(0, 0); CP_COMMIT();
    load_kv(1, 1); CP_COMMIT();

    const uint32_t ones2 = 0x3C003C00u;           // fp16 (1.0, 1.0)
    const uint32_t onesf[2] = { ones2, ones2 };

    float m0 = -1e30f, m1 = -1e30f, l0 = 0.f, l1 = 0.f;
    float oacc[16][4];
    #pragma unroll
    for (int i = 0; i < 16; i++)
        #pragma unroll
        for (int j = 0; j < 4; j++) oacc[i][j] = 0.f;

    #pragma unroll 1
    for (int kt = 0; kt < FD_NT; kt++) {
        CP_WAIT1();
        __syncthreads();
        const uint32_t Ks = sb + FD_K(kt & 1);
        const uint32_t Vs = sb + FD_V(kt & 1);
        const uint32_t kbase = Ks + ((((sub >> 1) << 3)) + l7) * ROWB;

        // ---- S = Q K^T (fp16, pre-scaled) ----
        float s[8][4];
        #pragma unroll
        for (int j = 0; j < 8; j++)
            #pragma unroll
            for (int q = 0; q < 4; q++) s[j][q] = 0.f;

        #pragma unroll
        for (int ks = 0; ks < 8; ks++) {
            const uint32_t ca = (2 * ks + (sub & 1)) * 16;
            #pragma unroll
            for (int p = 0; p < 4; p++) {
                uint32_t bf[4];
                ldm_x4(bf, kbase + p * 16 * ROWB + ca);
                mma_f16(s[2 * p],     qf[ks], bf);
                mma_f16(s[2 * p + 1], qf[ks], bf + 2);
            }
        }

        // ---- register softmax (f32 expf) ----
        float rmx0 = -1e30f, rmx1 = -1e30f;
        #pragma unroll
        for (int j = 0; j < 8; j++) {
            rmx0 = fmaxf(rmx0, fmaxf(s[j][0], s[j][1]));
            rmx1 = fmaxf(rmx1, fmaxf(s[j][2], s[j][3]));
        }
        rmx0 = fmaxf(rmx0, __shfl_xor_sync(0xffffffffu, rmx0, 1));
        rmx0 = fmaxf(rmx0, __shfl_xor_sync(0xffffffffu, rmx0, 2));
        rmx1 = fmaxf(rmx1, __shfl_xor_sync(0xffffffffu, rmx1, 1));
        rmx1 = fmaxf(rmx1, __shfl_xor_sync(0xffffffffu, rmx1, 2));

        float nm0 = fmaxf(m0, rmx0), nm1 = fmaxf(m1, rmx1);
        float a0 = __expf(m0 - nm0), a1 = __expf(m1 - nm1);
        m0 = nm0; m1 = nm1;

        #pragma unroll
        for (int j = 0; j < 8; j++) {
            s[j][0] = __expf(s[j][0] - nm0);
            s[j][1] = __expf(s[j][1] - nm0);
            s[j][2] = __expf(s[j][2] - nm1);
            s[j][3] = __expf(s[j][3] - nm1);
        }

        #pragma unroll
        for (int nb = 0; nb < 16; nb++) {
            oacc[nb][0] *= a0; oacc[nb][1] *= a0;
            oacc[nb][2] *= a1; oacc[nb][3] *= a1;
        }

        // ---- O += P @ V ; l via ones-mma (exact sums of applied P) ----
        float lacc[4] = {0.f, 0.f, 0.f, 0.f};
        #pragma unroll
        for (int kb = 0; kb < 4; kb++) {
            uint32_t a[4];
            a[0] = f22h2(s[2 * kb][0],     s[2 * kb][1]);
            a[1] = f22h2(s[2 * kb][2],     s[2 * kb][3]);
            a[2] = f22h2(s[2 * kb + 1][0], s[2 * kb + 1][1]);
            a[3] = f22h2(s[2 * kb + 1][2], s[2 * kb + 1][3]);
            mma_f16(lacc, a, onesf);
            const uint32_t vb = Vs + (kb * 16 + ((sub & 1) << 3) + l7) * ROWB
                              + (((sub >> 1) << 3)) * 2;
            #pragma unroll
            for (int nb = 0; nb < 16; nb += 2) {
                uint32_t bf[4];
                ldm_x4t(bf, vb + nb * 16);
                mma_f16(oacc[nb],     a, bf);
                mma_f16(oacc[nb + 1], a, bf + 2);
            }
        }
        l0 = l0 * a0 + lacc[0];
        l1 = l1 * a1 + lacc[2];

        __syncthreads();
        if (kt + 2 < FD_NT) load_kv(kt & 1, kt + 2);
        CP_COMMIT();
    }

    // ---- epilogue: O/l -> att fp16 ----
    const int g = lane >> 2, tq = lane & 3;
    const float inv0 = 1.f / l0, inv1 = 1.f / l1;
    __half* r0p = att + (size_t)(q0 + mw + g) * DIM + h * HDIM;
    __half* r1p = att + (size_t)(q0 + mw + g + 8) * DIM + h * HDIM;
    #pragma unroll
    for (int nb = 0; nb < 16; nb++) {
        int c = nb * 8 + tq * 2;
        *(__half2*)(r0p + c) =
            __floats2half2_rn(oacc[nb][0] * inv0, oacc[nb][1] * inv0);
        *(__half2*)(r1p + c) =
            __floats2half2_rn(oacc[nb][2] * inv1, oacc[nb][3] * inv1);
    }
}

// ===========================================================================
// kernel_launch
// ===========================================================================
extern "C" void kernel_launch(void* const* d_in, const int* in_sizes, int n_in,
                              void* d_out, int out_size)
{
    const float* hs     = (const float*)d_in[0];
    const float* cosf_  = (const float*)d_in[1];
    const float* sinf_  = (const float*)d_in[2];
    const float* w_qkv  = (const float*)d_in[3];
    const float* b_qkv  = (const float*)d_in[4];
    const float* w_qn   = (const float*)d_in[5];
    const float* w_kn   = (const float*)d_in[6];
    const float* w_out  = (const float*)d_in[7];
    const float* b_out  = (const float*)d_in[8];
    float* out = (float*)d_out;

    __half *hsH, *qk, *attF, *wqkvT, *woutT, *qF, *kF, *vH;
    cudaGetSymbolAddress((void**)&hsH,   g_hsH);
    cudaGetSymbolAddress((void**)&qk,    g_qk);
    cudaGetSymbolAddress((void**)&attF,  g_attF);
    cudaGetSymbolAddress((void**)&wqkvT, g_wqkvT);
    cudaGetSymbolAddress((void**)&woutT, g_woutT);
    cudaGetSymbolAddress((void**)&qF,    g_qF);
    cudaGetSymbolAddress((void**)&kF,    g_kF);
    cudaGetSymbolAddress((void**)&vH,    g_vH);

    cudaFuncSetAttribute(gemm_h,
                         cudaFuncAttributeMaxDynamicSharedMemorySize, G_SMEM);
    cudaFuncSetAttribute(fa_mma,
                         cudaFuncAttributeMaxDynamicSharedMemorySize, FD_SMEM);

    // --- pre-passes: weight transposes (fp16) + hs convert ---
    transpose_h<<<dim3(QKVW/32, DIM/32), dim3(32,8)>>>(w_qkv, wqkvT, QKVW);
    transpose_h<<<dim3(DIM/32,  DIM/32), dim3(32,8)>>>(w_out, woutT, DIM);
    convert_h<<<2048, 256>>>(hs, hsH, (S_LEN*DIM)/2);

    // --- qkv = hs @ w_qkv + b  (fp16; q,k -> g_qk, v -> vH) ---
    gemm_h<<<dim3(S_LEN/128, QKVW/128), 128, G_SMEM>>>(
        hsH, wqkvT, b_qkv, nullptr, qk, vH, QKVW, DIM);

    // --- rmsnorm + rope -> fp16 q/k per head (q pre-scaled) ---
    normrope_kernel<<<dim3(S_LEN, 2), 256>>>(qk, w_qn, w_kn, cosf_, sinf_,
                                             qF, kF);

    // --- flash attention -> att fp16 ---
    fa_mma<<<dim3(S_LEN/64, NHEAD), 128, FD_SMEM>>>(qF, kF, vH, attF);

    // --- out = att @ w_out + b  (fp16 in, fp32 out) ---
    gemm_h<<<dim3(S_LEN/128, DIM/128), 128, G_SMEM>>>(
        attF, woutT, b_out, out, nullptr, nullptr, DIM, DIM);
}